// round 2
// baseline (speedup 1.0000x reference)
#include <cuda_runtime.h>
#include <math.h>

#define BATCH 4
#define SEQ   2048
#define EMB   1024
#define NH    16
#define HD    64
#define MROWS (BATCH*SEQ)          // 8192
#define LDQKV (3*EMB)              // 3072
#define SPAD  68                   // smem row stride (floats) for attention tiles

// Scratch (allocation-free rules: __device__ globals)
__device__ float g_qkv[(size_t)MROWS * LDQKV];   // [8192][3072]  (q|k|v)
__device__ float g_att[(size_t)MROWS * EMB];     // [8192][1024]

// ---------------------------------------------------------------------------
// GEMM: C[M,N] = A[M,K] @ B[K,N] + bias[N]
// 128x128x16 tile, 256 threads, 8x8 micro-tile per thread.
// Assumes M%128==0, N%128==0, K%16==0 (true for all three calls here).
// ---------------------------------------------------------------------------
__global__ __launch_bounds__(256, 2)
void gemm_bias(const float* __restrict__ A, const float* __restrict__ Bm,
               const float* __restrict__ bias, float* __restrict__ Cm,
               int Mdim, int Ndim, int Kdim)
{
    __shared__ float As[16][132];   // As[k][m] (transposed A tile)
    __shared__ float Bs[16][132];   // Bs[k][n]

    const int tid = threadIdx.x;
    const int tx  = tid & 15;
    const int ty  = tid >> 4;
    const int m0  = blockIdx.y * 128;
    const int n0  = blockIdx.x * 128;

    float acc[8][8];
    #pragma unroll
    for (int i = 0; i < 8; i++)
        #pragma unroll
        for (int j = 0; j < 8; j++) acc[i][j] = 0.f;

    for (int k0 = 0; k0 < Kdim; k0 += 16) {
        // A tile: 128 rows x 16 cols = 512 float4
        #pragma unroll
        for (int t = 0; t < 2; t++) {
            int idx = tid + t * 256;
            int row = idx >> 2;           // 0..127
            int c4  = idx & 3;            // 0..3
            float4 v = *(const float4*)&A[(size_t)(m0 + row) * Kdim + k0 + c4 * 4];
            As[c4*4+0][row] = v.x;
            As[c4*4+1][row] = v.y;
            As[c4*4+2][row] = v.z;
            As[c4*4+3][row] = v.w;
        }
        // B tile: 16 rows x 128 cols = 512 float4
        #pragma unroll
        for (int t = 0; t < 2; t++) {
            int idx = tid + t * 256;
            int row = idx >> 5;           // 0..15
            int c4  = idx & 31;           // 0..31
            float4 v = *(const float4*)&Bm[(size_t)(k0 + row) * Ndim + n0 + c4 * 4];
            *(float4*)&Bs[row][c4 * 4] = v;
        }
        __syncthreads();

        #pragma unroll
        for (int kk = 0; kk < 16; kk++) {
            float a[8], b[8];
            *(float4*)&a[0] = *(const float4*)&As[kk][ty * 8];
            *(float4*)&a[4] = *(const float4*)&As[kk][ty * 8 + 4];
            *(float4*)&b[0] = *(const float4*)&Bs[kk][tx * 8];
            *(float4*)&b[4] = *(const float4*)&Bs[kk][tx * 8 + 4];
            #pragma unroll
            for (int i = 0; i < 8; i++)
                #pragma unroll
                for (int j = 0; j < 8; j++)
                    acc[i][j] += a[i] * b[j];
        }
        __syncthreads();
    }

    #pragma unroll
    for (int i = 0; i < 8; i++) {
        int row = m0 + ty * 8 + i;
        #pragma unroll
        for (int j = 0; j < 8; j += 4) {
            int col = n0 + tx * 8 + j;
            float4 v;
            v.x = acc[i][j+0] + bias[col+0];
            v.y = acc[i][j+1] + bias[col+1];
            v.z = acc[i][j+2] + bias[col+2];
            v.w = acc[i][j+3] + bias[col+3];
            *(float4*)&Cm[(size_t)row * Ndim + col] = v;
        }
    }
}

// ---------------------------------------------------------------------------
// Flash attention (fp32, causal). One block = (b, h, 64-query tile).
// 256 threads, 16x16 layout, each thread owns a 4(q) x 4 fragment.
// smem: Qst[d][q], Kst[d][k], Vs[k][d], Pst[k][q]  (stride SPAD=68)
// ---------------------------------------------------------------------------
__global__ __launch_bounds__(256)
void attn_kernel(const float* __restrict__ qkv, float* __restrict__ att)
{
    extern __shared__ float sm[];
    float* Qst  = sm;                   // 64*68
    float* Kst  = Qst  + 64 * SPAD;     // 64*68
    float* Vs   = Kst  + 64 * SPAD;     // 64*68
    float* Pst  = Vs   + 64 * SPAD;     // 64*68
    float* mrow = Pst  + 64 * SPAD;     // 64
    float* lrow = mrow + 64;            // 64
    float* arow = lrow + 64;            // 64
    float* red  = arow + 64;            // 64*16

    const int tid = threadIdx.x;
    const int tx  = tid & 15;
    const int ty  = tid >> 4;
    const int qt  = blockIdx.x;
    const int h   = blockIdx.y;
    const int b   = blockIdx.z;
    const int q0  = qt * 64;
    const size_t rowbase = (size_t)b * SEQ;
    const int colq = h * HD;
    const int colk = EMB + h * HD;
    const int colv = 2 * EMB + h * HD;

    // Load Q tile transposed: Qst[d][q]
    #pragma unroll
    for (int t = 0; t < 4; t++) {
        int idx = tid + t * 256;
        int r   = idx >> 4;             // 0..63 (query row)
        int c4  = idx & 15;             // 0..15 (d group)
        float4 v = *(const float4*)&qkv[(rowbase + q0 + r) * LDQKV + colq + c4 * 4];
        Qst[(c4*4+0) * SPAD + r] = v.x;
        Qst[(c4*4+1) * SPAD + r] = v.y;
        Qst[(c4*4+2) * SPAD + r] = v.z;
        Qst[(c4*4+3) * SPAD + r] = v.w;
    }
    if (tid < 64) { mrow[tid] = -1e30f; lrow[tid] = 0.f; }

    float o[4][4];
    #pragma unroll
    for (int i = 0; i < 4; i++)
        #pragma unroll
        for (int j = 0; j < 4; j++) o[i][j] = 0.f;

    for (int kt = 0; kt <= qt; kt++) {
        __syncthreads();   // previous tile's Pst/Vs/red consumers done; Q visible on 1st iter
        const int k0 = kt * 64;

        // Load K tile transposed + V tile
        #pragma unroll
        for (int t = 0; t < 4; t++) {
            int idx = tid + t * 256;
            int r   = idx >> 4;
            int c4  = idx & 15;
            const float* rowp = &qkv[(rowbase + k0 + r) * LDQKV];
            float4 kv = *(const float4*)&rowp[colk + c4 * 4];
            Kst[(c4*4+0) * SPAD + r] = kv.x;
            Kst[(c4*4+1) * SPAD + r] = kv.y;
            Kst[(c4*4+2) * SPAD + r] = kv.z;
            Kst[(c4*4+3) * SPAD + r] = kv.w;
            float4 vv = *(const float4*)&rowp[colv + c4 * 4];
            *(float4*)&Vs[r * SPAD + c4 * 4] = vv;
        }
        __syncthreads();

        // S = Q K^T  (thread: 4 q-rows [ty*4..], 4 k-cols [tx*4..])
        float s[4][4];
        #pragma unroll
        for (int i = 0; i < 4; i++)
            #pragma unroll
            for (int j = 0; j < 4; j++) s[i][j] = 0.f;

        #pragma unroll 8
        for (int d = 0; d < HD; d++) {
            float4 a  = *(const float4*)&Qst[d * SPAD + ty * 4];
            float4 bb = *(const float4*)&Kst[d * SPAD + tx * 4];
            float av[4] = {a.x, a.y, a.z, a.w};
            float bv[4] = {bb.x, bb.y, bb.z, bb.w};
            #pragma unroll
            for (int i = 0; i < 4; i++)
                #pragma unroll
                for (int j = 0; j < 4; j++)
                    s[i][j] += av[i] * bv[j];
        }
        #pragma unroll
        for (int i = 0; i < 4; i++)
            #pragma unroll
            for (int j = 0; j < 4; j++) s[i][j] *= 0.125f;   // 1/sqrt(64)

        if (kt == qt) {   // diagonal tile: causal mask (key > query)
            #pragma unroll
            for (int i = 0; i < 4; i++)
                #pragma unroll
                for (int j = 0; j < 4; j++)
                    if (tx * 4 + j > ty * 4 + i) s[i][j] = -1e30f;
        }

        // Row max (partial per thread -> smem reduce)
        #pragma unroll
        for (int i = 0; i < 4; i++) {
            float lm = fmaxf(fmaxf(s[i][0], s[i][1]), fmaxf(s[i][2], s[i][3]));
            red[(ty * 4 + i) * 16 + tx] = lm;
        }
        __syncthreads();
        if (tid < 64) {
            float tm = red[tid * 16];
            #pragma unroll
            for (int jj = 1; jj < 16; jj++) tm = fmaxf(tm, red[tid * 16 + jj]);
            float mn = fmaxf(mrow[tid], tm);
            arow[tid] = __expf(mrow[tid] - mn);
            mrow[tid] = mn;
        }
        __syncthreads();

        // P = exp(S - m), row sums, store P transposed: Pst[k][q]
        #pragma unroll
        for (int i = 0; i < 4; i++) {
            float mr = mrow[ty * 4 + i];
            float rs = 0.f;
            #pragma unroll
            for (int j = 0; j < 4; j++) {
                float p = __expf(s[i][j] - mr);
                rs += p;
                Pst[(tx * 4 + j) * SPAD + ty * 4 + i] = p;
            }
            red[(ty * 4 + i) * 16 + tx] = rs;
        }
        __syncthreads();
        if (tid < 64) {
            float rs = 0.f;
            #pragma unroll
            for (int jj = 0; jj < 16; jj++) rs += red[tid * 16 + jj];
            lrow[tid] = lrow[tid] * arow[tid] + rs;
        }

        // O = O*alpha + P @ V   (thread: 4 q-rows, 4 d-cols [tx*4..])
        #pragma unroll
        for (int i = 0; i < 4; i++) {
            float al = arow[ty * 4 + i];
            #pragma unroll
            for (int j = 0; j < 4; j++) o[i][j] *= al;
        }
        #pragma unroll 8
        for (int k = 0; k < 64; k++) {
            float4 p4 = *(const float4*)&Pst[k * SPAD + ty * 4];
            float4 v4 = *(const float4*)&Vs [k * SPAD + tx * 4];
            float pv[4] = {p4.x, p4.y, p4.z, p4.w};
            float vv[4] = {v4.x, v4.y, v4.z, v4.w};
            #pragma unroll
            for (int i = 0; i < 4; i++)
                #pragma unroll
                for (int j = 0; j < 4; j++)
                    o[i][j] += pv[i] * vv[j];
        }
    }
    __syncthreads();   // make final lrow visible

    #pragma unroll
    for (int i = 0; i < 4; i++) {
        int qr = ty * 4 + i;
        float inv = 1.f / lrow[qr];
        float4 v;
        v.x = o[i][0] * inv;
        v.y = o[i][1] * inv;
        v.z = o[i][2] * inv;
        v.w = o[i][3] * inv;
        *(float4*)&att[(rowbase + q0 + qr) * EMB + h * HD + tx * 4] = v;
    }
}

// ---------------------------------------------------------------------------
extern "C" void kernel_launch(void* const* d_in, const int* in_sizes, int n_in,
                              void* d_out, int out_size)
{
    const float* x      = (const float*)d_in[0];
    const float* w_attn = (const float*)d_in[1];
    const float* b_attn = (const float*)d_in[2];
    const float* w_proj = (const float*)d_in[3];
    const float* b_proj = (const float*)d_in[4];
    float* out = (float*)d_out;

    float* qkv = nullptr;
    float* att = nullptr;
    cudaGetSymbolAddress((void**)&qkv, g_qkv);
    cudaGetSymbolAddress((void**)&att, g_att);

    static const int ATTN_SMEM = (4 * 64 * SPAD + 3 * 64 + 64 * 16) * (int)sizeof(float);
    cudaFuncSetAttribute(attn_kernel, cudaFuncAttributeMaxDynamicSharedMemorySize, ATTN_SMEM);

    // 1) qkv = x @ w_attn + b_attn   [8192,1024]x[1024,3072]
    {
        dim3 grid(LDQKV / 128, MROWS / 128);
        gemm_bias<<<grid, 256>>>(x, w_attn, b_attn, qkv, MROWS, LDQKV, EMB);
    }
    // 2) flash attention per (b,h,qtile)
    {
        dim3 grid(SEQ / 64, NH, BATCH);
        attn_kernel<<<grid, 256, ATTN_SMEM>>>(qkv, att);
    }
    // 3) out = att @ w_proj + b_proj  [8192,1024]x[1024,1024]
    {
        dim3 grid(EMB / 128, MROWS / 128);
        gemm_bias<<<grid, 256>>>(att, w_proj, b_proj, out, MROWS, EMB, EMB);
    }
}

// round 4
// speedup vs baseline: 1.3659x; 1.3659x over previous
#include <cuda_runtime.h>
#include <math.h>
#include <stdint.h>

#define BATCH 4
#define SEQ   2048
#define EMB   1024
#define NH    16
#define HD    64
#define MROWS (BATCH*SEQ)          // 8192
#define LDQKV (3*EMB)              // 3072
#define SPAD  68                   // smem row stride (floats) for attention tiles

// GEMM tiling
#define BM 128
#define BN 256
#define BK 32
#define GT 256                     // threads per GEMM block
// smem float offsets (double buffered)
#define ASZ (8*128*4)              // 4096 floats per A buffer
#define BSTRIDE 264                // BN + 8  (8 mod 32 => conflict-free frag loads)
#define BSZ (32*BSTRIDE)           // 8448 floats per B buffer
#define GEMM_SMEM_FLOATS (2*ASZ + 2*BSZ)
#define GEMM_SMEM_BYTES  (GEMM_SMEM_FLOATS*4)

// Scratch (allocation-free rules: __device__ globals)
__device__ float g_qkv[(size_t)MROWS * LDQKV];   // [8192][3072]  (q|k|v)
__device__ float g_att[(size_t)MROWS * EMB];     // [8192][1024]

// ---------------------------------------------------------------------------
// helpers
// ---------------------------------------------------------------------------
__device__ __forceinline__ uint32_t f2tf32(float f) {
    uint32_t u;
    asm("cvt.rna.tf32.f32 %0, %1;" : "=r"(u) : "f"(f));
    return u;
}
__device__ __forceinline__ void cp16(uint32_t dst, const void* src) {
    asm volatile("cp.async.cg.shared.global [%0], [%1], 16;\n" :: "r"(dst), "l"(src));
}
__device__ __forceinline__ void cp_commit() {
    asm volatile("cp.async.commit_group;\n" ::: "memory");
}
__device__ __forceinline__ void cp_wait1() {
    asm volatile("cp.async.wait_group 1;\n" ::: "memory");
}
__device__ __forceinline__ void cp_wait0() {
    asm volatile("cp.async.wait_group 0;\n" ::: "memory");
}
__device__ __forceinline__ void mma_tf32(float* d, const uint32_t* a, const uint32_t* b) {
    asm volatile(
        "mma.sync.aligned.m16n8k8.row.col.f32.tf32.tf32.f32 "
        "{%0,%1,%2,%3}, {%4,%5,%6,%7}, {%8,%9}, {%0,%1,%2,%3};"
        : "+f"(d[0]), "+f"(d[1]), "+f"(d[2]), "+f"(d[3])
        : "r"(a[0]), "r"(a[1]), "r"(a[2]), "r"(a[3]), "r"(b[0]), "r"(b[1]));
}

// ---------------------------------------------------------------------------
// TF32 tensor-core GEMM: C[M,N] = A[M,K] @ B[K,N] + bias[N]
// Block tile 128x256x32, 8 warps (2x4), warp tile 64x64.
// A smem: chunked-XOR layout As4[g][m^g][j] (g=k>>2, j=k&3) -> conflict-free
//         16B stores AND conflict-free fragment loads.
// B smem: Bs[k][n], stride 264 -> conflict-free STS.128 + frag LDS.
// Double-buffered cp.async pipeline.
// Requires M%128==0, N%256==0, K%32==0 (holds: 8192x3072x1024, 8192x1024x1024).
// ---------------------------------------------------------------------------
__global__ __launch_bounds__(GT, 1)
void gemm_tf32(const float* __restrict__ A, const float* __restrict__ Bm,
               const float* __restrict__ bias, float* __restrict__ Cm,
               int Mdim, int Ndim, int Kdim)
{
    extern __shared__ float sm[];
    float* sA[2] = { sm,            sm + ASZ };
    float* sB[2] = { sm + 2*ASZ,    sm + 2*ASZ + BSZ };

    const int tid  = threadIdx.x;
    const int m0   = blockIdx.y * BM;
    const int n0   = blockIdx.x * BN;

    const int lane = tid & 31;
    const int tig  = lane & 3;        // thread-in-group
    const int grp  = lane >> 2;       // group id (0..7)
    const int mw   = (tid >> 7) * 64;         // warp m offset (0,64)
    const int nw   = ((tid >> 5) & 3) * 64;   // warp n offset (0,64,128,192)

    // global-load decomposition
    const int a_c4 = tid & 7;         // which 16B chunk of the 32-float A row
    const int a_rb = tid >> 3;        // A row base (0..31)
    const int b_kb = tid >> 6;        // B k base (0..3)
    const int b_c4 = tid & 63;        // B 16B chunk within 256-float row

    const float* aG = A  + (size_t)(m0 + a_rb) * Kdim + a_c4 * 4;
    const float* bG = Bm + (size_t)b_kb * Ndim + n0 + b_c4 * 4;

    // precompute smem byte addresses for cp.async destinations
    uint32_t sAaddr[2][4], sBaddr[2][8];
    #pragma unroll
    for (int bf = 0; bf < 2; bf++) {
        #pragma unroll
        for (int i = 0; i < 4; i++) {
            int row = a_rb + 32 * i;
            sAaddr[bf][i] = (uint32_t)__cvta_generic_to_shared(
                sA[bf] + a_c4 * 512 + ((row ^ a_c4) << 2));
        }
        #pragma unroll
        for (int i = 0; i < 8; i++) {
            int k = b_kb + 4 * i;
            sBaddr[bf][i] = (uint32_t)__cvta_generic_to_shared(
                sB[bf] + k * BSTRIDE + b_c4 * 4);
        }
    }

    float acc[4][8][4];
    #pragma unroll
    for (int mi = 0; mi < 4; mi++)
        #pragma unroll
        for (int ni = 0; ni < 8; ni++)
            #pragma unroll
            for (int c = 0; c < 4; c++) acc[mi][ni][c] = 0.f;

    const int NT = Kdim / BK;

    // prologue: load tile 0 into buffer 0
    {
        #pragma unroll
        for (int i = 0; i < 4; i++)
            cp16(sAaddr[0][i], aG + (size_t)(32 * i) * Kdim);
        #pragma unroll
        for (int i = 0; i < 8; i++)
            cp16(sBaddr[0][i], bG + (size_t)(4 * i) * Ndim);
        cp_commit();
    }

    for (int t = 0; t < NT; t++) {
        const int buf = t & 1;
        if (t + 1 < NT) {
            const int nb = (t + 1) & 1;
            const int koff = (t + 1) * BK;
            #pragma unroll
            for (int i = 0; i < 4; i++)
                cp16(sAaddr[nb][i], aG + (size_t)(32 * i) * Kdim + koff);
            #pragma unroll
            for (int i = 0; i < 8; i++)
                cp16(sBaddr[nb][i], bG + (size_t)(4 * i + koff) * Ndim);
            cp_commit();
            cp_wait1();
        } else {
            cp_wait0();
        }
        __syncthreads();

        const float* cA = sA[buf];
        const float* cB = sB[buf];

        #pragma unroll
        for (int s = 0; s < 4; s++) {
            const int g0 = 2 * s, g1 = 2 * s + 1;
            uint32_t afr[4][4];
            #pragma unroll
            for (int mi = 0; mi < 4; mi++) {
                int m = mw + 16 * mi + grp;
                afr[mi][0] = f2tf32(cA[g0 * 512 + ((m    ) ^ g0) * 4 + tig]);
                afr[mi][1] = f2tf32(cA[g0 * 512 + ((m + 8) ^ g0) * 4 + tig]);
                afr[mi][2] = f2tf32(cA[g1 * 512 + ((m    ) ^ g1) * 4 + tig]);
                afr[mi][3] = f2tf32(cA[g1 * 512 + ((m + 8) ^ g1) * 4 + tig]);
            }
            uint32_t bfr[8][2];
            #pragma unroll
            for (int ni = 0; ni < 8; ni++) {
                int n = nw + 8 * ni + grp;
                bfr[ni][0] = f2tf32(cB[(8 * s + tig    ) * BSTRIDE + n]);
                bfr[ni][1] = f2tf32(cB[(8 * s + tig + 4) * BSTRIDE + n]);
            }
            #pragma unroll
            for (int mi = 0; mi < 4; mi++)
                #pragma unroll
                for (int ni = 0; ni < 8; ni++)
                    mma_tf32(acc[mi][ni], afr[mi], bfr[ni]);
        }
        __syncthreads();
    }

    // epilogue: bias + store (float2 per c-frag half)
    float bl0[8], bl1[8];
    #pragma unroll
    for (int ni = 0; ni < 8; ni++) {
        int col = n0 + nw + 8 * ni + 2 * tig;
        bl0[ni] = bias[col];
        bl1[ni] = bias[col + 1];
    }
    #pragma unroll
    for (int mi = 0; mi < 4; mi++) {
        int row = m0 + mw + 16 * mi + grp;
        #pragma unroll
        for (int ni = 0; ni < 8; ni++) {
            int col = n0 + nw + 8 * ni + 2 * tig;
            float2 v0 = { acc[mi][ni][0] + bl0[ni], acc[mi][ni][1] + bl1[ni] };
            *(float2*)&Cm[(size_t)row * Ndim + col] = v0;
            float2 v1 = { acc[mi][ni][2] + bl0[ni], acc[mi][ni][3] + bl1[ni] };
            *(float2*)&Cm[(size_t)(row + 8) * Ndim + col] = v1;
        }
    }
}

// ---------------------------------------------------------------------------
// Flash attention (fp32, causal). One block = (b, h, 64-query tile).
// 256 threads, 16x16 layout, each thread owns a 4(q) x 4 fragment.
// ---------------------------------------------------------------------------
__global__ __launch_bounds__(256)
void attn_kernel(const float* __restrict__ qkv, float* __restrict__ att)
{
    extern __shared__ float smf[];
    float* Qst  = smf;                  // 64*68
    float* Kst  = Qst  + 64 * SPAD;     // 64*68
    float* Vs   = Kst  + 64 * SPAD;     // 64*68
    float* Pst  = Vs   + 64 * SPAD;     // 64*68
    float* mrow = Pst  + 64 * SPAD;     // 64
    float* lrow = mrow + 64;            // 64
    float* arow = lrow + 64;            // 64
    float* red  = arow + 64;            // 64*16

    const int tid = threadIdx.x;
    const int tx  = tid & 15;
    const int ty  = tid >> 4;
    const int qt  = blockIdx.x;
    const int h   = blockIdx.y;
    const int b   = blockIdx.z;
    const int q0  = qt * 64;
    const size_t rowbase = (size_t)b * SEQ;
    const int colq = h * HD;
    const int colk = EMB + h * HD;
    const int colv = 2 * EMB + h * HD;

    #pragma unroll
    for (int t = 0; t < 4; t++) {
        int idx = tid + t * 256;
        int r   = idx >> 4;
        int c4  = idx & 15;
        float4 v = *(const float4*)&qkv[(rowbase + q0 + r) * LDQKV + colq + c4 * 4];
        Qst[(c4*4+0) * SPAD + r] = v.x;
        Qst[(c4*4+1) * SPAD + r] = v.y;
        Qst[(c4*4+2) * SPAD + r] = v.z;
        Qst[(c4*4+3) * SPAD + r] = v.w;
    }
    if (tid < 64) { mrow[tid] = -1e30f; lrow[tid] = 0.f; }

    float o[4][4];
    #pragma unroll
    for (int i = 0; i < 4; i++)
        #pragma unroll
        for (int j = 0; j < 4; j++) o[i][j] = 0.f;

    for (int kt = 0; kt <= qt; kt++) {
        __syncthreads();
        const int k0 = kt * 64;

        #pragma unroll
        for (int t = 0; t < 4; t++) {
            int idx = tid + t * 256;
            int r   = idx >> 4;
            int c4  = idx & 15;
            const float* rowp = &qkv[(rowbase + k0 + r) * LDQKV];
            float4 kv = *(const float4*)&rowp[colk + c4 * 4];
            Kst[(c4*4+0) * SPAD + r] = kv.x;
            Kst[(c4*4+1) * SPAD + r] = kv.y;
            Kst[(c4*4+2) * SPAD + r] = kv.z;
            Kst[(c4*4+3) * SPAD + r] = kv.w;
            float4 vv = *(const float4*)&rowp[colv + c4 * 4];
            *(float4*)&Vs[r * SPAD + c4 * 4] = vv;
        }
        __syncthreads();

        float s[4][4];
        #pragma unroll
        for (int i = 0; i < 4; i++)
            #pragma unroll
            for (int j = 0; j < 4; j++) s[i][j] = 0.f;

        #pragma unroll 8
        for (int d = 0; d < HD; d++) {
            float4 a  = *(const float4*)&Qst[d * SPAD + ty * 4];
            float4 bb = *(const float4*)&Kst[d * SPAD + tx * 4];
            float av[4] = {a.x, a.y, a.z, a.w};
            float bv[4] = {bb.x, bb.y, bb.z, bb.w};
            #pragma unroll
            for (int i = 0; i < 4; i++)
                #pragma unroll
                for (int j = 0; j < 4; j++)
                    s[i][j] += av[i] * bv[j];
        }
        #pragma unroll
        for (int i = 0; i < 4; i++)
            #pragma unroll
            for (int j = 0; j < 4; j++) s[i][j] *= 0.125f;

        if (kt == qt) {
            #pragma unroll
            for (int i = 0; i < 4; i++)
                #pragma unroll
                for (int j = 0; j < 4; j++)
                    if (tx * 4 + j > ty * 4 + i) s[i][j] = -1e30f;
        }

        #pragma unroll
        for (int i = 0; i < 4; i++) {
            float lm = fmaxf(fmaxf(s[i][0], s[i][1]), fmaxf(s[i][2], s[i][3]));
            red[(ty * 4 + i) * 16 + tx] = lm;
        }
        __syncthreads();
        if (tid < 64) {
            float tm = red[tid * 16];
            #pragma unroll
            for (int jj = 1; jj < 16; jj++) tm = fmaxf(tm, red[tid * 16 + jj]);
            float mn = fmaxf(mrow[tid], tm);
            arow[tid] = __expf(mrow[tid] - mn);
            mrow[tid] = mn;
        }
        __syncthreads();

        #pragma unroll
        for (int i = 0; i < 4; i++) {
            float mr = mrow[ty * 4 + i];
            float rs = 0.f;
            #pragma unroll
            for (int j = 0; j < 4; j++) {
                float p = __expf(s[i][j] - mr);
                rs += p;
                Pst[(tx * 4 + j) * SPAD + ty * 4 + i] = p;
            }
            red[(ty * 4 + i) * 16 + tx] = rs;
        }
        __syncthreads();
        if (tid < 64) {
            float rs = 0.f;
            #pragma unroll
            for (int jj = 0; jj < 16; jj++) rs += red[tid * 16 + jj];
            lrow[tid] = lrow[tid] * arow[tid] + rs;
        }

        #pragma unroll
        for (int i = 0; i < 4; i++) {
            float al = arow[ty * 4 + i];
            #pragma unroll
            for (int j = 0; j < 4; j++) o[i][j] *= al;
        }
        #pragma unroll 8
        for (int k = 0; k < 64; k++) {
            float4 p4 = *(const float4*)&Pst[k * SPAD + ty * 4];
            float4 v4 = *(const float4*)&Vs [k * SPAD + tx * 4];
            float pv[4] = {p4.x, p4.y, p4.z, p4.w};
            float vv[4] = {v4.x, v4.y, v4.z, v4.w};
            #pragma unroll
            for (int i = 0; i < 4; i++)
                #pragma unroll
                for (int j = 0; j < 4; j++)
                    o[i][j] += pv[i] * vv[j];
        }
    }
    __syncthreads();

    #pragma unroll
    for (int i = 0; i < 4; i++) {
        int qr = ty * 4 + i;
        float inv = 1.f / lrow[qr];
        float4 v;
        v.x = o[i][0] * inv;
        v.y = o[i][1] * inv;
        v.z = o[i][2] * inv;
        v.w = o[i][3] * inv;
        *(float4*)&att[(rowbase + q0 + qr) * EMB + h * HD + tx * 4] = v;
    }
}

// ---------------------------------------------------------------------------
extern "C" void kernel_launch(void* const* d_in, const int* in_sizes, int n_in,
                              void* d_out, int out_size)
{
    const float* x      = (const float*)d_in[0];
    const float* w_attn = (const float*)d_in[1];
    const float* b_attn = (const float*)d_in[2];
    const float* w_proj = (const float*)d_in[3];
    const float* b_proj = (const float*)d_in[4];
    float* out = (float*)d_out;

    float* qkv = nullptr;
    float* att = nullptr;
    cudaGetSymbolAddress((void**)&qkv, g_qkv);
    cudaGetSymbolAddress((void**)&att, g_att);

    static const int ATTN_SMEM = (4 * 64 * SPAD + 3 * 64 + 64 * 16) * (int)sizeof(float);
    cudaFuncSetAttribute(attn_kernel, cudaFuncAttributeMaxDynamicSharedMemorySize, ATTN_SMEM);
    cudaFuncSetAttribute(gemm_tf32, cudaFuncAttributeMaxDynamicSharedMemorySize, GEMM_SMEM_BYTES);

    // 1) qkv = x @ w_attn + b_attn   [8192,1024]x[1024,3072]
    {
        dim3 grid(LDQKV / BN, MROWS / BM);
        gemm_tf32<<<grid, GT, GEMM_SMEM_BYTES>>>(x, w_attn, b_attn, qkv, MROWS, LDQKV, EMB);
    }
    // 2) flash attention per (b,h,qtile)
    {
        dim3 grid(SEQ / 64, NH, BATCH);
        attn_kernel<<<grid, 256, ATTN_SMEM>>>(qkv, att);
    }
    // 3) out = att @ w_proj + b_proj  [8192,1024]x[1024,1024]
    {
        dim3 grid(EMB / BN, MROWS / BM);
        gemm_tf32<<<grid, GT, GEMM_SMEM_BYTES>>>(att, w_proj, b_proj, out, MROWS, EMB, EMB);
    }
}

// round 5
// speedup vs baseline: 2.8314x; 2.0729x over previous
#include <cuda_runtime.h>
#include <math.h>
#include <stdint.h>

#define BATCH 4
#define SEQ   2048
#define EMB   1024
#define NH    16
#define HD    64
#define MROWS (BATCH*SEQ)          // 8192
#define LDQKV (3*EMB)              // 3072

// GEMM tiling
#define BM 128
#define BN 256
#define BK 32
#define GT 256
#define ASZ (8*128*4)              // 4096 floats per A stage
#define BSTRIDE 264                // BN + 8
#define BSZ (32*BSTRIDE)           // 8448 floats per B stage
#define NSTAGE 3
#define STAGE_FLOATS (ASZ + BSZ)
#define GEMM_SMEM_BYTES (NSTAGE*STAGE_FLOATS*4)

// attention tiling
#define APAD 68
#define VPAD 72
#define ATTN_SMEM_FLOATS (128*APAD + 64*APAD + 64*VPAD + 128*APAD)
#define ATTN_SMEM_BYTES  (ATTN_SMEM_FLOATS*4)

// Scratch (__device__ globals per allocation rules)
__device__ float g_qkv[(size_t)MROWS * LDQKV];   // rounded qkv
__device__ float g_att[(size_t)MROWS * EMB];     // rounded attention out
__device__ float g_xt [(size_t)MROWS * EMB];     // tf32-rounded x
__device__ float g_wat[(size_t)EMB * LDQKV];     // tf32-rounded w_attn
__device__ float g_wpt[(size_t)EMB * EMB];       // tf32-rounded w_proj

// ---------------------------------------------------------------------------
__device__ __forceinline__ uint32_t f2tf32(float f) {
    uint32_t u;
    asm("cvt.rna.tf32.f32 %0, %1;" : "=r"(u) : "f"(f));
    return u;
}
__device__ __forceinline__ float roundtf(float f) { return __uint_as_float(f2tf32(f)); }
__device__ __forceinline__ void cp16(uint32_t dst, const void* src) {
    asm volatile("cp.async.cg.shared.global [%0], [%1], 16;\n" :: "r"(dst), "l"(src));
}
__device__ __forceinline__ void cp_commit() {
    asm volatile("cp.async.commit_group;\n" ::: "memory");
}
__device__ __forceinline__ void cp_wait2() {
    asm volatile("cp.async.wait_group 2;\n" ::: "memory");
}
__device__ __forceinline__ void mma_tf32(float* d, const uint32_t* a, const uint32_t* b) {
    asm volatile(
        "mma.sync.aligned.m16n8k8.row.col.f32.tf32.tf32.f32 "
        "{%0,%1,%2,%3}, {%4,%5,%6,%7}, {%8,%9}, {%0,%1,%2,%3};"
        : "+f"(d[0]), "+f"(d[1]), "+f"(d[2]), "+f"(d[3])
        : "r"(a[0]), "r"(a[1]), "r"(a[2]), "r"(a[3]), "r"(b[0]), "r"(b[1]));
}

// ---------------------------------------------------------------------------
// elementwise tf32 rounding prepass
// ---------------------------------------------------------------------------
__global__ void round_tf32_kernel(const float* __restrict__ src, float* __restrict__ dst, int n4)
{
    int i = blockIdx.x * blockDim.x + threadIdx.x;
    if (i < n4) {
        float4 v = ((const float4*)src)[i];
        v.x = roundtf(v.x); v.y = roundtf(v.y);
        v.z = roundtf(v.z); v.w = roundtf(v.w);
        ((float4*)dst)[i] = v;
    }
}

// ---------------------------------------------------------------------------
// TF32 tensor-core GEMM, operands pre-rounded. C = A@B + bias, optional
// tf32 rounding of the output. 128x256x32, 8 warps, 3-stage cp.async.
// ---------------------------------------------------------------------------
__global__ __launch_bounds__(GT, 1)
void gemm_tf32(const float* __restrict__ A, const float* __restrict__ Bm,
               const float* __restrict__ bias, float* __restrict__ Cm,
               int Ndim, int Kdim, int round_out)
{
    extern __shared__ float sm[];

    const int tid  = threadIdx.x;
    const int m0   = blockIdx.y * BM;
    const int n0   = blockIdx.x * BN;

    const int lane = tid & 31;
    const int tig  = lane & 3;
    const int grp  = lane >> 2;
    const int mw   = (tid >> 7) * 64;
    const int nw   = ((tid >> 5) & 3) * 64;

    const int a_c4 = tid & 7;
    const int a_rb = tid >> 3;
    const int b_kb = tid >> 6;
    const int b_c4 = tid & 63;

    const float* aG = A  + (size_t)(m0 + a_rb) * Kdim + a_c4 * 4;
    const float* bG = Bm + (size_t)b_kb * Ndim + n0 + b_c4 * 4;

    // stage-0 smem byte addresses
    uint32_t sA0[4], sB0[8];
    #pragma unroll
    for (int i = 0; i < 4; i++) {
        int row = a_rb + 32 * i;
        sA0[i] = (uint32_t)__cvta_generic_to_shared(
            sm + a_c4 * 512 + ((row ^ a_c4) << 2));
    }
    #pragma unroll
    for (int i = 0; i < 8; i++) {
        int k = b_kb + 4 * i;
        sB0[i] = (uint32_t)__cvta_generic_to_shared(
            sm + ASZ + k * BSTRIDE + b_c4 * 4);
    }
    const uint32_t stageB = STAGE_FLOATS * 4;

    float acc[4][8][4];
    #pragma unroll
    for (int mi = 0; mi < 4; mi++)
        #pragma unroll
        for (int ni = 0; ni < 8; ni++)
            #pragma unroll
            for (int c = 0; c < 4; c++) acc[mi][ni][c] = 0.f;

    const int NT = Kdim / BK;

    // prologue: tiles 0 and 1
    #pragma unroll
    for (int p = 0; p < 2; p++) {
        uint32_t so = p * stageB;
        int koff = p * BK;
        #pragma unroll
        for (int i = 0; i < 4; i++)
            cp16(sA0[i] + so, aG + (size_t)(32 * i) * Kdim + koff);
        #pragma unroll
        for (int i = 0; i < 8; i++)
            cp16(sB0[i] + so, bG + (size_t)(4 * i + koff) * Ndim);
        cp_commit();
    }

    for (int t = 0; t < NT; t++) {
        if (t + 2 < NT) {
            uint32_t so = ((t + 2) % NSTAGE) * stageB;
            int koff = (t + 2) * BK;
            #pragma unroll
            for (int i = 0; i < 4; i++)
                cp16(sA0[i] + so, aG + (size_t)(32 * i) * Kdim + koff);
            #pragma unroll
            for (int i = 0; i < 8; i++)
                cp16(sB0[i] + so, bG + (size_t)(4 * i + koff) * Ndim);
        }
        cp_commit();
        cp_wait2();
        __syncthreads();

        const float* cA = sm + (t % NSTAGE) * STAGE_FLOATS;
        const float* cB = cA + ASZ;

        #pragma unroll
        for (int s = 0; s < 4; s++) {
            const int g0 = 2 * s, g1 = 2 * s + 1;
            uint32_t afr[4][4];
            #pragma unroll
            for (int mi = 0; mi < 4; mi++) {
                int m = mw + 16 * mi + grp;
                afr[mi][0] = __float_as_uint(cA[g0 * 512 + ((m    ) ^ g0) * 4 + tig]);
                afr[mi][1] = __float_as_uint(cA[g0 * 512 + ((m + 8) ^ g0) * 4 + tig]);
                afr[mi][2] = __float_as_uint(cA[g1 * 512 + ((m    ) ^ g1) * 4 + tig]);
                afr[mi][3] = __float_as_uint(cA[g1 * 512 + ((m + 8) ^ g1) * 4 + tig]);
            }
            uint32_t bfr[8][2];
            #pragma unroll
            for (int ni = 0; ni < 8; ni++) {
                int n = nw + 8 * ni + grp;
                bfr[ni][0] = __float_as_uint(cB[(8 * s + tig    ) * BSTRIDE + n]);
                bfr[ni][1] = __float_as_uint(cB[(8 * s + tig + 4) * BSTRIDE + n]);
            }
            #pragma unroll
            for (int mi = 0; mi < 4; mi++)
                #pragma unroll
                for (int ni = 0; ni < 8; ni++)
                    mma_tf32(acc[mi][ni], afr[mi], bfr[ni]);
        }
        __syncthreads();
    }

    float bl0[8], bl1[8];
    #pragma unroll
    for (int ni = 0; ni < 8; ni++) {
        int col = n0 + nw + 8 * ni + 2 * tig;
        bl0[ni] = bias[col];
        bl1[ni] = bias[col + 1];
    }
    #pragma unroll
    for (int mi = 0; mi < 4; mi++) {
        int row = m0 + mw + 16 * mi + grp;
        #pragma unroll
        for (int ni = 0; ni < 8; ni++) {
            int col = n0 + nw + 8 * ni + 2 * tig;
            float2 v0 = { acc[mi][ni][0] + bl0[ni], acc[mi][ni][1] + bl1[ni] };
            float2 v1 = { acc[mi][ni][2] + bl0[ni], acc[mi][ni][3] + bl1[ni] };
            if (round_out) {
                v0.x = roundtf(v0.x); v0.y = roundtf(v0.y);
                v1.x = roundtf(v1.x); v1.y = roundtf(v1.y);
            }
            *(float2*)&Cm[(size_t)row * Ndim + col] = v0;
            *(float2*)&Cm[(size_t)(row + 8) * Ndim + col] = v1;
        }
    }
}

// ---------------------------------------------------------------------------
// Tensor-core flash attention (tf32 mma, fp32 softmax), causal.
// Block = (qtile of 128, h, b). 8 warps; warp w owns query rows [w*16, w*16+16).
// ---------------------------------------------------------------------------
__global__ __launch_bounds__(256)
void attn_mma(const float* __restrict__ qkv, float* __restrict__ att)
{
    extern __shared__ float smf[];
    float* Qs = smf;                          // 128 x APAD
    float* Ks = Qs + 128 * APAD;              // 64 x APAD
    float* Vs = Ks + 64 * APAD;               // 64 x VPAD
    float* Ps = Vs + 64 * VPAD;               // 128 x APAD (per-warp 16-row slabs)

    const int tid  = threadIdx.x;
    const int lane = tid & 31;
    const int w    = tid >> 5;
    const int tig  = lane & 3;
    const int grp  = lane >> 2;
    const int qt = blockIdx.x, h = blockIdx.y, b = blockIdx.z;
    const int q0 = qt * 128;
    const size_t rowbase = (size_t)b * SEQ;
    const int colq = h * HD, colk = EMB + h * HD, colv = 2 * EMB + h * HD;

    // load Q tile (128 x 64)
    #pragma unroll
    for (int t = 0; t < 8; t++) {
        int idx = tid + t * 256;
        int r = idx >> 4, c4 = idx & 15;
        *(float4*)&Qs[r * APAD + c4 * 4] =
            *(const float4*)&qkv[(rowbase + q0 + r) * LDQKV + colq + c4 * 4];
    }
    __syncthreads();

    // hoist Q fragments for all 8 k-steps
    uint32_t qa[8][4];
    #pragma unroll
    for (int kk = 0; kk < 8; kk++) {
        const float* q0p = &Qs[(w * 16 + grp    ) * APAD + kk * 8];
        const float* q1p = &Qs[(w * 16 + grp + 8) * APAD + kk * 8];
        qa[kk][0] = __float_as_uint(q0p[tig]);
        qa[kk][1] = __float_as_uint(q1p[tig]);
        qa[kk][2] = __float_as_uint(q0p[tig + 4]);
        qa[kk][3] = __float_as_uint(q1p[tig + 4]);
    }

    float o[8][4];
    #pragma unroll
    for (int ni = 0; ni < 8; ni++)
        #pragma unroll
        for (int c = 0; c < 4; c++) o[ni][c] = 0.f;
    float m0 = -1e30f, m1 = -1e30f, l0 = 0.f, l1 = 0.f;

    const int r0g = q0 + w * 16 + grp;      // global query row for c0/c1
    const int r1g = r0g + 8;                // for c2/c3

    const int nkt = 2 * qt + 2;
    for (int kt = 0; kt < nkt; kt++) {
        const int k0 = kt * 64;
        __syncthreads();
        // load K, V tiles (64 x 64 each)
        #pragma unroll
        for (int t = 0; t < 4; t++) {
            int idx = tid + t * 256;
            int r = idx >> 4, c4 = idx & 15;
            const float* rowp = &qkv[(rowbase + k0 + r) * LDQKV];
            *(float4*)&Ks[r * APAD + c4 * 4] = *(const float4*)&rowp[colk + c4 * 4];
            *(float4*)&Vs[r * VPAD + c4 * 4] = *(const float4*)&rowp[colv + c4 * 4];
        }
        __syncthreads();

        // S = Q K^T
        float s[8][4];
        #pragma unroll
        for (int ni = 0; ni < 8; ni++)
            #pragma unroll
            for (int c = 0; c < 4; c++) s[ni][c] = 0.f;
        #pragma unroll
        for (int kk = 0; kk < 8; kk++) {
            #pragma unroll
            for (int ni = 0; ni < 8; ni++) {
                const float* kp = &Ks[(ni * 8 + grp) * APAD + kk * 8];
                uint32_t bfr[2];
                bfr[0] = __float_as_uint(kp[tig]);
                bfr[1] = __float_as_uint(kp[tig + 4]);
                mma_tf32(s[ni], qa[kk], bfr);
            }
        }
        #pragma unroll
        for (int ni = 0; ni < 8; ni++)
            #pragma unroll
            for (int c = 0; c < 4; c++) s[ni][c] *= 0.125f;

        if (k0 + 63 > r0g) {    // causal mask (only diagonal tiles trigger)
            #pragma unroll
            for (int ni = 0; ni < 8; ni++) {
                int c0 = k0 + ni * 8 + 2 * tig;
                if (c0     > r0g) s[ni][0] = -1e30f;
                if (c0 + 1 > r0g) s[ni][1] = -1e30f;
                if (c0     > r1g) s[ni][2] = -1e30f;
                if (c0 + 1 > r1g) s[ni][3] = -1e30f;
            }
        }

        // row max (quad shfl reduce over tig lanes)
        float pm0 = -1e30f, pm1 = -1e30f;
        #pragma unroll
        for (int ni = 0; ni < 8; ni++) {
            pm0 = fmaxf(pm0, fmaxf(s[ni][0], s[ni][1]));
            pm1 = fmaxf(pm1, fmaxf(s[ni][2], s[ni][3]));
        }
        pm0 = fmaxf(pm0, __shfl_xor_sync(0xffffffffu, pm0, 1));
        pm0 = fmaxf(pm0, __shfl_xor_sync(0xffffffffu, pm0, 2));
        pm1 = fmaxf(pm1, __shfl_xor_sync(0xffffffffu, pm1, 1));
        pm1 = fmaxf(pm1, __shfl_xor_sync(0xffffffffu, pm1, 2));
        float mn0 = fmaxf(m0, pm0), mn1 = fmaxf(m1, pm1);
        float a0 = __expf(m0 - mn0), a1 = __expf(m1 - mn1);
        m0 = mn0; m1 = mn1;

        // P = exp(S - m): accumulate sums, store rounded P to warp slab
        float rs0 = 0.f, rs1 = 0.f;
        float* p0p = &Ps[(w * 16 + grp    ) * APAD + 2 * tig];
        float* p1p = &Ps[(w * 16 + grp + 8) * APAD + 2 * tig];
        #pragma unroll
        for (int ni = 0; ni < 8; ni++) {
            float e0 = __expf(s[ni][0] - mn0);
            float e1 = __expf(s[ni][1] - mn0);
            float e2 = __expf(s[ni][2] - mn1);
            float e3 = __expf(s[ni][3] - mn1);
            rs0 += e0 + e1; rs1 += e2 + e3;
            float2 w0 = { roundtf(e0), roundtf(e1) };
            float2 w1 = { roundtf(e2), roundtf(e3) };
            *(float2*)&p0p[ni * 8] = w0;
            *(float2*)&p1p[ni * 8] = w1;
        }
        rs0 += __shfl_xor_sync(0xffffffffu, rs0, 1);
        rs0 += __shfl_xor_sync(0xffffffffu, rs0, 2);
        rs1 += __shfl_xor_sync(0xffffffffu, rs1, 1);
        rs1 += __shfl_xor_sync(0xffffffffu, rs1, 2);
        l0 = l0 * a0 + rs0;
        l1 = l1 * a1 + rs1;

        // rescale O
        #pragma unroll
        for (int ni = 0; ni < 8; ni++) {
            o[ni][0] *= a0; o[ni][1] *= a0;
            o[ni][2] *= a1; o[ni][3] *= a1;
        }
        __syncwarp();

        // O += P @ V
        #pragma unroll
        for (int kk = 0; kk < 8; kk++) {
            const float* pa0 = &Ps[(w * 16 + grp    ) * APAD + kk * 8];
            const float* pa1 = &Ps[(w * 16 + grp + 8) * APAD + kk * 8];
            uint32_t pa[4];
            pa[0] = __float_as_uint(pa0[tig]);
            pa[1] = __float_as_uint(pa1[tig]);
            pa[2] = __float_as_uint(pa0[tig + 4]);
            pa[3] = __float_as_uint(pa1[tig + 4]);
            #pragma unroll
            for (int ni = 0; ni < 8; ni++) {
                uint32_t bfr[2];
                bfr[0] = __float_as_uint(Vs[(kk * 8 + tig    ) * VPAD + ni * 8 + grp]);
                bfr[1] = __float_as_uint(Vs[(kk * 8 + tig + 4) * VPAD + ni * 8 + grp]);
                mma_tf32(o[ni], pa, bfr);
            }
        }
    }

    // epilogue: normalize, round to tf32, store
    float inv0 = 1.f / l0, inv1 = 1.f / l1;
    #pragma unroll
    for (int ni = 0; ni < 8; ni++) {
        int col = h * HD + ni * 8 + 2 * tig;
        float2 v0 = { roundtf(o[ni][0] * inv0), roundtf(o[ni][1] * inv0) };
        float2 v1 = { roundtf(o[ni][2] * inv1), roundtf(o[ni][3] * inv1) };
        *(float2*)&att[(rowbase + r0g) * EMB + col] = v0;
        *(float2*)&att[(rowbase + r1g) * EMB + col] = v1;
    }
}

// ---------------------------------------------------------------------------
extern "C" void kernel_launch(void* const* d_in, const int* in_sizes, int n_in,
                              void* d_out, int out_size)
{
    const float* x      = (const float*)d_in[0];
    const float* w_attn = (const float*)d_in[1];
    const float* b_attn = (const float*)d_in[2];
    const float* w_proj = (const float*)d_in[3];
    const float* b_proj = (const float*)d_in[4];
    float* out = (float*)d_out;

    float *qkv, *att, *xt, *wat, *wpt;
    cudaGetSymbolAddress((void**)&qkv, g_qkv);
    cudaGetSymbolAddress((void**)&att, g_att);
    cudaGetSymbolAddress((void**)&xt,  g_xt);
    cudaGetSymbolAddress((void**)&wat, g_wat);
    cudaGetSymbolAddress((void**)&wpt, g_wpt);

    cudaFuncSetAttribute(gemm_tf32, cudaFuncAttributeMaxDynamicSharedMemorySize, GEMM_SMEM_BYTES);
    cudaFuncSetAttribute(attn_mma,  cudaFuncAttributeMaxDynamicSharedMemorySize, ATTN_SMEM_BYTES);

    // 0) tf32 rounding prepass
    round_tf32_kernel<<<(MROWS * EMB / 4 + 255) / 256, 256>>>(x, xt, MROWS * EMB / 4);
    round_tf32_kernel<<<(EMB * LDQKV / 4 + 255) / 256, 256>>>(w_attn, wat, EMB * LDQKV / 4);
    round_tf32_kernel<<<(EMB * EMB / 4 + 255) / 256, 256>>>(w_proj, wpt, EMB * EMB / 4);

    // 1) qkv = x @ w_attn + b_attn   (output rounded to tf32)
    {
        dim3 grid(LDQKV / BN, MROWS / BM);
        gemm_tf32<<<grid, GT, GEMM_SMEM_BYTES>>>(xt, wat, b_attn, qkv, LDQKV, EMB, 1);
    }
    // 2) tensor-core flash attention (output rounded to tf32)
    {
        dim3 grid(SEQ / 128, NH, BATCH);
        attn_mma<<<grid, 256, ATTN_SMEM_BYTES>>>(qkv, att);
    }
    // 3) out = att @ w_proj + b_proj (final fp32)
    {
        dim3 grid(EMB / BN, MROWS / BM);
        gemm_tf32<<<grid, GT, GEMM_SMEM_BYTES>>>(att, wpt, b_proj, out, EMB, EMB, 0);
    }
}

// round 7
// speedup vs baseline: 2.8844x; 1.0187x over previous
#include <cuda_runtime.h>
#include <math.h>
#include <stdint.h>

#define BATCH 4
#define SEQ   2048
#define EMB   1024
#define NH    16
#define HD    64
#define MROWS (BATCH*SEQ)          // 8192
#define LDQKV (3*EMB)              // 3072

// GEMM tiling: 128x256x32 CTA tile, 16 warps (4x4), warp tile 32x64
#define BM 128
#define BN 256
#define BK 32
#define GT 512
#define ASZ (8*128*4)              // 4096 floats per A stage
#define BSTRIDE 264                // BN + 8
#define BSZ (32*BSTRIDE)           // 8448 floats per B stage
#define NSTAGE 3
#define STAGE_FLOATS (ASZ + BSZ)
#define GEMM_SMEM_BYTES (NSTAGE*STAGE_FLOATS*4)

// attention tiling
#define APAD 68
#define VPAD 72
#define ATTN_SMEM_FLOATS (128*APAD + 64*APAD + 64*VPAD + 128*APAD)
#define ATTN_SMEM_BYTES  (ATTN_SMEM_FLOATS*4)

// Scratch (__device__ globals per allocation rules)
__device__ float g_qkv[(size_t)MROWS * LDQKV];
__device__ float g_att[(size_t)MROWS * EMB];
__device__ float g_xt [(size_t)MROWS * EMB];
__device__ float g_wat[(size_t)EMB * LDQKV];
__device__ float g_wpt[(size_t)EMB * EMB];

// ---------------------------------------------------------------------------
__device__ __forceinline__ uint32_t f2tf32(float f) {
    uint32_t u;
    asm("cvt.rna.tf32.f32 %0, %1;" : "=r"(u) : "f"(f));
    return u;
}
__device__ __forceinline__ float roundtf(float f) { return __uint_as_float(f2tf32(f)); }
__device__ __forceinline__ void cp16(uint32_t dst, const void* src) {
    asm volatile("cp.async.cg.shared.global [%0], [%1], 16;\n" :: "r"(dst), "l"(src));
}
__device__ __forceinline__ void cp_commit() {
    asm volatile("cp.async.commit_group;\n" ::: "memory");
}
__device__ __forceinline__ void cp_wait2() {
    asm volatile("cp.async.wait_group 2;\n" ::: "memory");
}
__device__ __forceinline__ void mma_tf32(float* d, const uint32_t* a, const uint32_t* b) {
    asm volatile(
        "mma.sync.aligned.m16n8k8.row.col.f32.tf32.tf32.f32 "
        "{%0,%1,%2,%3}, {%4,%5,%6,%7}, {%8,%9}, {%0,%1,%2,%3};"
        : "+f"(d[0]), "+f"(d[1]), "+f"(d[2]), "+f"(d[3])
        : "r"(a[0]), "r"(a[1]), "r"(a[2]), "r"(a[3]), "r"(b[0]), "r"(b[1]));
}

// ---------------------------------------------------------------------------
__global__ void round_tf32_kernel(const float* __restrict__ src, float* __restrict__ dst, int n4)
{
    int i = blockIdx.x * blockDim.x + threadIdx.x;
    if (i < n4) {
        float4 v = ((const float4*)src)[i];
        v.x = roundtf(v.x); v.y = roundtf(v.y);
        v.z = roundtf(v.z); v.w = roundtf(v.w);
        ((float4*)dst)[i] = v;
    }
}

// ---------------------------------------------------------------------------
// TF32 tensor-core GEMM, pre-rounded operands. 128x256x32, 16 warps,
// warp tile 32x64, 3-stage cp.async pipeline.
// ---------------------------------------------------------------------------
__global__ __launch_bounds__(GT, 1)
void gemm_tf32(const float* __restrict__ A, const float* __restrict__ Bm,
               const float* __restrict__ bias, float* __restrict__ Cm,
               int Ndim, int Kdim, int round_out)
{
    extern __shared__ float sm[];

    const int tid  = threadIdx.x;
    const int m0   = blockIdx.y * BM;
    const int n0   = blockIdx.x * BN;

    const int lane = tid & 31;
    const int tig  = lane & 3;
    const int grp  = lane >> 2;
    const int wid  = tid >> 5;                // 0..15
    const int mw   = (wid >> 2) * 32;         // 0,32,64,96
    const int nw   = (wid & 3) * 64;          // 0,64,128,192

    // global-load decomposition (512 threads)
    const int a_c4 = tid & 7;                 // 16B chunk in 32-float A row
    const int a_rb = tid >> 3;                // 0..63 (rows a_rb, a_rb+64)
    const int b_kb = tid >> 6;                // 0..7  (k rows b_kb + 8i)
    const int b_c4 = tid & 63;                // 16B chunk in 256-float B row

    const float* aG = A  + (size_t)(m0 + a_rb) * Kdim + a_c4 * 4;
    const float* bG = Bm + (size_t)b_kb * Ndim + n0 + b_c4 * 4;

    uint32_t sA0[2], sB0[4];
    #pragma unroll
    for (int i = 0; i < 2; i++) {
        int row = a_rb + 64 * i;
        sA0[i] = (uint32_t)__cvta_generic_to_shared(
            sm + a_c4 * 512 + ((row ^ a_c4) << 2));
    }
    #pragma unroll
    for (int i = 0; i < 4; i++) {
        int k = b_kb + 8 * i;
        sB0[i] = (uint32_t)__cvta_generic_to_shared(
            sm + ASZ + k * BSTRIDE + b_c4 * 4);
    }
    const uint32_t stageB = STAGE_FLOATS * 4;

    float acc[2][8][4];
    #pragma unroll
    for (int mi = 0; mi < 2; mi++)
        #pragma unroll
        for (int ni = 0; ni < 8; ni++)
            #pragma unroll
            for (int c = 0; c < 4; c++) acc[mi][ni][c] = 0.f;

    const int NT = Kdim / BK;

    #pragma unroll
    for (int p = 0; p < 2; p++) {
        uint32_t so = p * stageB;
        int koff = p * BK;
        #pragma unroll
        for (int i = 0; i < 2; i++)
            cp16(sA0[i] + so, aG + (size_t)(64 * i) * Kdim + koff);
        #pragma unroll
        for (int i = 0; i < 4; i++)
            cp16(sB0[i] + so, bG + (size_t)(8 * i + koff) * Ndim);
        cp_commit();
    }

    for (int t = 0; t < NT; t++) {
        if (t + 2 < NT) {
            uint32_t so = ((t + 2) % NSTAGE) * stageB;
            int koff = (t + 2) * BK;
            #pragma unroll
            for (int i = 0; i < 2; i++)
                cp16(sA0[i] + so, aG + (size_t)(64 * i) * Kdim + koff);
            #pragma unroll
            for (int i = 0; i < 4; i++)
                cp16(sB0[i] + so, bG + (size_t)(8 * i + koff) * Ndim);
        }
        cp_commit();
        cp_wait2();
        __syncthreads();

        const float* cA = sm + (t % NSTAGE) * STAGE_FLOATS;
        const float* cB = cA + ASZ;

        #pragma unroll
        for (int s = 0; s < 4; s++) {
            const int g0 = 2 * s, g1 = 2 * s + 1;
            uint32_t afr[2][4];
            #pragma unroll
            for (int mi = 0; mi < 2; mi++) {
                int m = mw + 16 * mi + grp;
                afr[mi][0] = __float_as_uint(cA[g0 * 512 + ((m    ) ^ g0) * 4 + tig]);
                afr[mi][1] = __float_as_uint(cA[g0 * 512 + ((m + 8) ^ g0) * 4 + tig]);
                afr[mi][2] = __float_as_uint(cA[g1 * 512 + ((m    ) ^ g1) * 4 + tig]);
                afr[mi][3] = __float_as_uint(cA[g1 * 512 + ((m + 8) ^ g1) * 4 + tig]);
            }
            uint32_t bfr[8][2];
            #pragma unroll
            for (int ni = 0; ni < 8; ni++) {
                int n = nw + 8 * ni + grp;
                bfr[ni][0] = __float_as_uint(cB[(8 * s + tig    ) * BSTRIDE + n]);
                bfr[ni][1] = __float_as_uint(cB[(8 * s + tig + 4) * BSTRIDE + n]);
            }
            #pragma unroll
            for (int mi = 0; mi < 2; mi++)
                #pragma unroll
                for (int ni = 0; ni < 8; ni++)
                    mma_tf32(acc[mi][ni], afr[mi], bfr[ni]);
        }
        __syncthreads();
    }

    float bl0[8], bl1[8];
    #pragma unroll
    for (int ni = 0; ni < 8; ni++) {
        int col = n0 + nw + 8 * ni + 2 * tig;
        bl0[ni] = bias[col];
        bl1[ni] = bias[col + 1];
    }
    #pragma unroll
    for (int mi = 0; mi < 2; mi++) {
        int row = m0 + mw + 16 * mi + grp;
        #pragma unroll
        for (int ni = 0; ni < 8; ni++) {
            int col = n0 + nw + 8 * ni + 2 * tig;
            float2 v0 = { acc[mi][ni][0] + bl0[ni], acc[mi][ni][1] + bl1[ni] };
            float2 v1 = { acc[mi][ni][2] + bl0[ni], acc[mi][ni][3] + bl1[ni] };
            if (round_out) {
                v0.x = roundtf(v0.x); v0.y = roundtf(v0.y);
                v1.x = roundtf(v1.x); v1.y = roundtf(v1.y);
            }
            *(float2*)&Cm[(size_t)row * Ndim + col] = v0;
            *(float2*)&Cm[(size_t)(row + 8) * Ndim + col] = v1;
        }
    }
}

// ---------------------------------------------------------------------------
// Tensor-core flash attention (tf32 mma, fp32 softmax), causal.
// ---------------------------------------------------------------------------
__global__ __launch_bounds__(256)
void attn_mma(const float* __restrict__ qkv, float* __restrict__ att)
{
    extern __shared__ float smf[];
    float* Qs = smf;                          // 128 x APAD
    float* Ks = Qs + 128 * APAD;              // 64 x APAD
    float* Vs = Ks + 64 * APAD;               // 64 x VPAD
    float* Ps = Vs + 64 * VPAD;               // 128 x APAD

    const int tid  = threadIdx.x;
    const int lane = tid & 31;
    const int w    = tid >> 5;
    const int tig  = lane & 3;
    const int grp  = lane >> 2;
    const int qt = blockIdx.x, h = blockIdx.y, b = blockIdx.z;
    const int q0 = qt * 128;
    const size_t rowbase = (size_t)b * SEQ;
    const int colq = h * HD, colk = EMB + h * HD, colv = 2 * EMB + h * HD;

    #pragma unroll
    for (int t = 0; t < 8; t++) {
        int idx = tid + t * 256;
        int r = idx >> 4, c4 = idx & 15;
        *(float4*)&Qs[r * APAD + c4 * 4] =
            *(const float4*)&qkv[(rowbase + q0 + r) * LDQKV + colq + c4 * 4];
    }
    __syncthreads();

    uint32_t qa[8][4];
    #pragma unroll
    for (int kk = 0; kk < 8; kk++) {
        const float* q0p = &Qs[(w * 16 + grp    ) * APAD + kk * 8];
        const float* q1p = &Qs[(w * 16 + grp + 8) * APAD + kk * 8];
        qa[kk][0] = __float_as_uint(q0p[tig]);
        qa[kk][1] = __float_as_uint(q1p[tig]);
        qa[kk][2] = __float_as_uint(q0p[tig + 4]);
        qa[kk][3] = __float_as_uint(q1p[tig + 4]);
    }

    float o[8][4];
    #pragma unroll
    for (int ni = 0; ni < 8; ni++)
        #pragma unroll
        for (int c = 0; c < 4; c++) o[ni][c] = 0.f;
    float m0 = -1e30f, m1 = -1e30f, l0 = 0.f, l1 = 0.f;

    const int r0g = q0 + w * 16 + grp;
    const int r1g = r0g + 8;

    const int nkt = 2 * qt + 2;
    for (int kt = 0; kt < nkt; kt++) {
        const int k0 = kt * 64;
        __syncthreads();
        #pragma unroll
        for (int t = 0; t < 4; t++) {
            int idx = tid + t * 256;
            int r = idx >> 4, c4 = idx & 15;
            const float* rowp = &qkv[(rowbase + k0 + r) * LDQKV];
            *(float4*)&Ks[r * APAD + c4 * 4] = *(const float4*)&rowp[colk + c4 * 4];
            *(float4*)&Vs[r * VPAD + c4 * 4] = *(const float4*)&rowp[colv + c4 * 4];
        }
        __syncthreads();

        float s[8][4];
        #pragma unroll
        for (int ni = 0; ni < 8; ni++)
            #pragma unroll
            for (int c = 0; c < 4; c++) s[ni][c] = 0.f;
        #pragma unroll
        for (int kk = 0; kk < 8; kk++) {
            #pragma unroll
            for (int ni = 0; ni < 8; ni++) {
                const float* kp = &Ks[(ni * 8 + grp) * APAD + kk * 8];
                uint32_t bfr[2];
                bfr[0] = __float_as_uint(kp[tig]);
                bfr[1] = __float_as_uint(kp[tig + 4]);
                mma_tf32(s[ni], qa[kk], bfr);
            }
        }
        #pragma unroll
        for (int ni = 0; ni < 8; ni++)
            #pragma unroll
            for (int c = 0; c < 4; c++) s[ni][c] *= 0.125f;

        if (k0 + 63 > r0g) {
            #pragma unroll
            for (int ni = 0; ni < 8; ni++) {
                int c0 = k0 + ni * 8 + 2 * tig;
                if (c0     > r0g) s[ni][0] = -1e30f;
                if (c0 + 1 > r0g) s[ni][1] = -1e30f;
                if (c0     > r1g) s[ni][2] = -1e30f;
                if (c0 + 1 > r1g) s[ni][3] = -1e30f;
            }
        }

        float pm0 = -1e30f, pm1 = -1e30f;
        #pragma unroll
        for (int ni = 0; ni < 8; ni++) {
            pm0 = fmaxf(pm0, fmaxf(s[ni][0], s[ni][1]));
            pm1 = fmaxf(pm1, fmaxf(s[ni][2], s[ni][3]));
        }
        pm0 = fmaxf(pm0, __shfl_xor_sync(0xffffffffu, pm0, 1));
        pm0 = fmaxf(pm0, __shfl_xor_sync(0xffffffffu, pm0, 2));
        pm1 = fmaxf(pm1, __shfl_xor_sync(0xffffffffu, pm1, 1));
        pm1 = fmaxf(pm1, __shfl_xor_sync(0xffffffffu, pm1, 2));
        float mn0 = fmaxf(m0, pm0), mn1 = fmaxf(m1, pm1);
        float a0 = __expf(m0 - mn0), a1 = __expf(m1 - mn1);
        m0 = mn0; m1 = mn1;

        float rs0 = 0.f, rs1 = 0.f;
        float* p0p = &Ps[(w * 16 + grp    ) * APAD + 2 * tig];
        float* p1p = &Ps[(w * 16 + grp + 8) * APAD + 2 * tig];
        #pragma unroll
        for (int ni = 0; ni < 8; ni++) {
            float e0 = __expf(s[ni][0] - mn0);
            float e1 = __expf(s[ni][1] - mn0);
            float e2 = __expf(s[ni][2] - mn1);
            float e3 = __expf(s[ni][3] - mn1);
            rs0 += e0 + e1; rs1 += e2 + e3;
            float2 w0 = { roundtf(e0), roundtf(e1) };
            float2 w1 = { roundtf(e2), roundtf(e3) };
            *(float2*)&p0p[ni * 8] = w0;
            *(float2*)&p1p[ni * 8] = w1;
        }
        rs0 += __shfl_xor_sync(0xffffffffu, rs0, 1);
        rs0 += __shfl_xor_sync(0xffffffffu, rs0, 2);
        rs1 += __shfl_xor_sync(0xffffffffu, rs1, 1);
        rs1 += __shfl_xor_sync(0xffffffffu, rs1, 2);
        l0 = l0 * a0 + rs0;
        l1 = l1 * a1 + rs1;

        #pragma unroll
        for (int ni = 0; ni < 8; ni++) {
            o[ni][0] *= a0; o[ni][1] *= a0;
            o[ni][2] *= a1; o[ni][3] *= a1;
        }
        __syncwarp();

        #pragma unroll
        for (int kk = 0; kk < 8; kk++) {
            const float* pa0 = &Ps[(w * 16 + grp    ) * APAD + kk * 8];
            const float* pa1 = &Ps[(w * 16 + grp + 8) * APAD + kk * 8];
            uint32_t pa[4];
            pa[0] = __float_as_uint(pa0[tig]);
            pa[1] = __float_as_uint(pa1[tig]);
            pa[2] = __float_as_uint(pa0[tig + 4]);
            pa[3] = __float_as_uint(pa1[tig + 4]);
            #pragma unroll
            for (int ni = 0; ni < 8; ni++) {
                uint32_t bfr[2];
                bfr[0] = __float_as_uint(Vs[(kk * 8 + tig    ) * VPAD + ni * 8 + grp]);
                bfr[1] = __float_as_uint(Vs[(kk * 8 + tig + 4) * VPAD + ni * 8 + grp]);
                mma_tf32(o[ni], pa, bfr);
            }
        }
    }

    float inv0 = 1.f / l0, inv1 = 1.f / l1;
    #pragma unroll
    for (int ni = 0; ni < 8; ni++) {
        int col = h * HD + ni * 8 + 2 * tig;
        float2 v0 = { roundtf(o[ni][0] * inv0), roundtf(o[ni][1] * inv0) };
        float2 v1 = { roundtf(o[ni][2] * inv1), roundtf(o[ni][3] * inv1) };
        *(float2*)&att[(rowbase + r0g) * EMB + col] = v0;
        *(float2*)&att[(rowbase + r1g) * EMB + col] = v1;
    }
}

// ---------------------------------------------------------------------------
extern "C" void kernel_launch(void* const* d_in, const int* in_sizes, int n_in,
                              void* d_out, int out_size)
{
    const float* x      = (const float*)d_in[0];
    const float* w_attn = (const float*)d_in[1];
    const float* b_attn = (const float*)d_in[2];
    const float* w_proj = (const float*)d_in[3];
    const float* b_proj = (const float*)d_in[4];
    float* out = (float*)d_out;

    float *qkv, *att, *xt, *wat, *wpt;
    cudaGetSymbolAddress((void**)&qkv, g_qkv);
    cudaGetSymbolAddress((void**)&att, g_att);
    cudaGetSymbolAddress((void**)&xt,  g_xt);
    cudaGetSymbolAddress((void**)&wat, g_wat);
    cudaGetSymbolAddress((void**)&wpt, g_wpt);

    cudaFuncSetAttribute(gemm_tf32, cudaFuncAttributeMaxDynamicSharedMemorySize, GEMM_SMEM_BYTES);
    cudaFuncSetAttribute(attn_mma,  cudaFuncAttributeMaxDynamicSharedMemorySize, ATTN_SMEM_BYTES);

    // 0) tf32 rounding prepass
    round_tf32_kernel<<<(MROWS * EMB / 4 + 255) / 256, 256>>>(x, xt, MROWS * EMB / 4);
    round_tf32_kernel<<<(EMB * LDQKV / 4 + 255) / 256, 256>>>(w_attn, wat, EMB * LDQKV / 4);
    round_tf32_kernel<<<(EMB * EMB / 4 + 255) / 256, 256>>>(w_proj, wpt, EMB * EMB / 4);

    // 1) qkv = x @ w_attn + b_attn
    {
        dim3 grid(LDQKV / BN, MROWS / BM);
        gemm_tf32<<<grid, GT, GEMM_SMEM_BYTES>>>(xt, wat, b_attn, qkv, LDQKV, EMB, 1);
    }
    // 2) tensor-core flash attention
    {
        dim3 grid(SEQ / 128, NH, BATCH);
        attn_mma<<<grid, 256, ATTN_SMEM_BYTES>>>(qkv, att);
    }
    // 3) out = att @ w_proj + b_proj
    {
        dim3 grid(EMB / BN, MROWS / BM);
        gemm_tf32<<<grid, GT, GEMM_SMEM_BYTES>>>(att, wpt, b_proj, out, EMB, EMB, 0);
    }
}

// round 11
// speedup vs baseline: 2.9571x; 1.0252x over previous
#include <cuda_runtime.h>
#include <math.h>
#include <stdint.h>

#define BATCH 4
#define SEQ   2048
#define EMB   1024
#define NH    16
#define HD    64
#define MROWS (BATCH*SEQ)          // 8192
#define LDQKV (3*EMB)              // 3072

// GEMM tiling: 128x256x32 CTA tile, 16 warps (4x4), warp tile 32x64
#define BM 128
#define BN 256
#define BK 32
#define GT 512
#define ASZ (8*128*4)              // 4096 floats per A stage
#define BSTRIDE 264                // BN + 8
#define BSZ (32*BSTRIDE)           // 8448 floats per B stage
#define NSTAGE 3
#define STAGE_FLOATS (ASZ + BSZ)
#define GEMM_SMEM_BYTES (NSTAGE*STAGE_FLOATS*4)

// attention tiling: Q slab reused as P slab -> 70.6 KB -> 2 CTAs/SM
#define APAD 68
#define VPAD 72
#define ATTN_SMEM_FLOATS (128*APAD + 64*APAD + 64*VPAD)
#define ATTN_SMEM_BYTES  (ATTN_SMEM_FLOATS*4)

// Scratch (__device__ globals per allocation rules)
__device__ float g_qkv[(size_t)MROWS * LDQKV];
__device__ float g_att[(size_t)MROWS * EMB];
__device__ float g_xt [(size_t)MROWS * EMB];
__device__ float g_wat[(size_t)EMB * LDQKV];
__device__ float g_wpt[(size_t)EMB * EMB];

// ---------------------------------------------------------------------------
__device__ __forceinline__ uint32_t f2tf32(float f) {
    uint32_t u;
    asm("cvt.rna.tf32.f32 %0, %1;" : "=r"(u) : "f"(f));
    return u;
}
__device__ __forceinline__ float roundtf(float f) { return __uint_as_float(f2tf32(f)); }
__device__ __forceinline__ void cp16(uint32_t dst, const void* src) {
    asm volatile("cp.async.cg.shared.global [%0], [%1], 16;\n" :: "r"(dst), "l"(src));
}
__device__ __forceinline__ void cp_commit() {
    asm volatile("cp.async.commit_group;\n" ::: "memory");
}
__device__ __forceinline__ void cp_wait1() {
    asm volatile("cp.async.wait_group 1;\n" ::: "memory");
}
__device__ __forceinline__ void cp_wait0() {
    asm volatile("cp.async.wait_group 0;\n" ::: "memory");
}
__device__ __forceinline__ uint32_t smem_u32(const void* p) {
    return (uint32_t)__cvta_generic_to_shared(p);
}
__device__ __forceinline__ void mma_tf32(float* d, const uint32_t* a, const uint32_t* b) {
    asm volatile(
        "mma.sync.aligned.m16n8k8.row.col.f32.tf32.tf32.f32 "
        "{%0,%1,%2,%3}, {%4,%5,%6,%7}, {%8,%9}, {%0,%1,%2,%3};"
        : "+f"(d[0]), "+f"(d[1]), "+f"(d[2]), "+f"(d[3])
        : "r"(a[0]), "r"(a[1]), "r"(a[2]), "r"(a[3]), "r"(b[0]), "r"(b[1]));
}

// ---------------------------------------------------------------------------
__global__ void round_tf32_kernel(const float* __restrict__ src, float* __restrict__ dst, int n4)
{
    int i = blockIdx.x * blockDim.x + threadIdx.x;
    if (i < n4) {
        float4 v = ((const float4*)src)[i];
        v.x = roundtf(v.x); v.y = roundtf(v.y);
        v.z = roundtf(v.z); v.w = roundtf(v.w);
        ((float4*)dst)[i] = v;
    }
}

// ---------------------------------------------------------------------------
// TF32 tensor-core GEMM, pre-rounded operands. 128x256x32, 16 warps,
// warp tile 32x64, 3-stage cp.async pipeline, ONE barrier per k-tile.
// Per-iter order: wait(tile t) -> sync -> prefetch t+2 -> commit -> compute t.
// The sync guarantees all warps finished compute t-1 (whose buffer (t-1)%3 ==
// (t+2)%3 is the prefetch target), making the single barrier race-free.
// ---------------------------------------------------------------------------
__global__ __launch_bounds__(GT, 1)
void gemm_tf32(const float* __restrict__ A, const float* __restrict__ Bm,
               const float* __restrict__ bias, float* __restrict__ Cm,
               int Ndim, int Kdim, int round_out)
{
    extern __shared__ float sm[];

    const int tid  = threadIdx.x;
    const int m0   = blockIdx.y * BM;
    const int n0   = blockIdx.x * BN;

    const int lane = tid & 31;
    const int tig  = lane & 3;
    const int grp  = lane >> 2;
    const int wid  = tid >> 5;
    const int mw   = (wid >> 2) * 32;
    const int nw   = (wid & 3) * 64;

    const int a_c4 = tid & 7;
    const int a_rb = tid >> 3;
    const int b_kb = tid >> 6;
    const int b_c4 = tid & 63;

    const float* aG = A  + (size_t)(m0 + a_rb) * Kdim + a_c4 * 4;
    const float* bG = Bm + (size_t)b_kb * Ndim + n0 + b_c4 * 4;

    uint32_t sA0[2], sB0[4];
    #pragma unroll
    for (int i = 0; i < 2; i++) {
        int row = a_rb + 64 * i;
        sA0[i] = (uint32_t)__cvta_generic_to_shared(
            sm + a_c4 * 512 + ((row ^ a_c4) << 2));
    }
    #pragma unroll
    for (int i = 0; i < 4; i++) {
        int k = b_kb + 8 * i;
        sB0[i] = (uint32_t)__cvta_generic_to_shared(
            sm + ASZ + k * BSTRIDE + b_c4 * 4);
    }
    const uint32_t stageB = STAGE_FLOATS * 4;

    float acc[2][8][4];
    #pragma unroll
    for (int mi = 0; mi < 2; mi++)
        #pragma unroll
        for (int ni = 0; ni < 8; ni++)
            #pragma unroll
            for (int c = 0; c < 4; c++) acc[mi][ni][c] = 0.f;

    const int NT = Kdim / BK;

    // prologue: tiles 0,1 into stages 0,1 (one commit each)
    #pragma unroll
    for (int p = 0; p < 2; p++) {
        uint32_t so = p * stageB;
        int koff = p * BK;
        #pragma unroll
        for (int i = 0; i < 2; i++)
            cp16(sA0[i] + so, aG + (size_t)(64 * i) * Kdim + koff);
        #pragma unroll
        for (int i = 0; i < 4; i++)
            cp16(sB0[i] + so, bG + (size_t)(8 * i + koff) * Ndim);
        cp_commit();
    }

    for (int t = 0; t < NT; t++) {
        cp_wait1();          // tile t's group complete
        __syncthreads();     // all warps done with tile t-1; t's data visible
        if (t + 2 < NT) {
            uint32_t so = ((t + 2) % NSTAGE) * stageB;
            int koff = (t + 2) * BK;
            #pragma unroll
            for (int i = 0; i < 2; i++)
                cp16(sA0[i] + so, aG + (size_t)(64 * i) * Kdim + koff);
            #pragma unroll
            for (int i = 0; i < 4; i++)
                cp16(sB0[i] + so, bG + (size_t)(8 * i + koff) * Ndim);
        }
        cp_commit();         // uniform group counting (empty at tail)

        const float* cA = sm + (t % NSTAGE) * STAGE_FLOATS;
        const float* cB = cA + ASZ;

        #pragma unroll
        for (int s = 0; s < 4; s++) {
            const int g0 = 2 * s, g1 = 2 * s + 1;
            uint32_t afr[2][4];
            #pragma unroll
            for (int mi = 0; mi < 2; mi++) {
                int m = mw + 16 * mi + grp;
                afr[mi][0] = __float_as_uint(cA[g0 * 512 + ((m    ) ^ g0) * 4 + tig]);
                afr[mi][1] = __float_as_uint(cA[g0 * 512 + ((m + 8) ^ g0) * 4 + tig]);
                afr[mi][2] = __float_as_uint(cA[g1 * 512 + ((m    ) ^ g1) * 4 + tig]);
                afr[mi][3] = __float_as_uint(cA[g1 * 512 + ((m + 8) ^ g1) * 4 + tig]);
            }
            uint32_t bfr[8][2];
            #pragma unroll
            for (int ni = 0; ni < 8; ni++) {
                int n = nw + 8 * ni + grp;
                bfr[ni][0] = __float_as_uint(cB[(8 * s + tig    ) * BSTRIDE + n]);
                bfr[ni][1] = __float_as_uint(cB[(8 * s + tig + 4) * BSTRIDE + n]);
            }
            #pragma unroll
            for (int mi = 0; mi < 2; mi++)
                #pragma unroll
                for (int ni = 0; ni < 8; ni++)
                    mma_tf32(acc[mi][ni], afr[mi], bfr[ni]);
        }
    }

    float bl0[8], bl1[8];
    #pragma unroll
    for (int ni = 0; ni < 8; ni++) {
        int col = n0 + nw + 8 * ni + 2 * tig;
        bl0[ni] = bias[col];
        bl1[ni] = bias[col + 1];
    }
    #pragma unroll
    for (int mi = 0; mi < 2; mi++) {
        int row = m0 + mw + 16 * mi + grp;
        #pragma unroll
        for (int ni = 0; ni < 8; ni++) {
            int col = n0 + nw + 8 * ni + 2 * tig;
            float2 v0 = { acc[mi][ni][0] + bl0[ni], acc[mi][ni][1] + bl1[ni] };
            float2 v1 = { acc[mi][ni][2] + bl0[ni], acc[mi][ni][3] + bl1[ni] };
            if (round_out) {
                v0.x = roundtf(v0.x); v0.y = roundtf(v0.y);
                v1.x = roundtf(v1.x); v1.y = roundtf(v1.y);
            }
            *(float2*)&Cm[(size_t)row * Ndim + col] = v0;
            *(float2*)&Cm[(size_t)(row + 8) * Ndim + col] = v1;
        }
    }
}

// ---------------------------------------------------------------------------
// Tensor-core flash attention (tf32 mma.sync, fp32 softmax), causal.
// P slab aliases the Q slab (Q fragments are register-resident after the
// prologue; each warp only writes its own 16 rows). 70.6 KB smem -> 2 CTA/SM.
// K/V tiles loaded via cp.async.
// ---------------------------------------------------------------------------
__global__ __launch_bounds__(256, 2)
void attn_mma(const float* __restrict__ qkv, float* __restrict__ att)
{
    extern __shared__ float smf[];
    float* Qs = smf;                          // 128 x APAD (reused as Ps)
    float* Ps = smf;
    float* Ks = Qs + 128 * APAD;              // 64 x APAD
    float* Vs = Ks + 64 * APAD;               // 64 x VPAD

    const int tid  = threadIdx.x;
    const int lane = tid & 31;
    const int w    = tid >> 5;
    const int tig  = lane & 3;
    const int grp  = lane >> 2;
    const int qt = blockIdx.x, h = blockIdx.y, b = blockIdx.z;
    const int q0 = qt * 128;
    const size_t rowbase = (size_t)b * SEQ;
    const int colq = h * HD, colk = EMB + h * HD, colv = 2 * EMB + h * HD;

    // load Q tile via cp.async
    {
        #pragma unroll
        for (int t = 0; t < 8; t++) {
            int idx = tid + t * 256;
            int r = idx >> 4, c4 = idx & 15;
            cp16(smem_u32(&Qs[r * APAD + c4 * 4]),
                 &qkv[(rowbase + q0 + r) * LDQKV + colq + c4 * 4]);
        }
        cp_commit();
        cp_wait0();
        __syncthreads();
    }

    // hoist Q fragments for all 8 k-steps
    uint32_t qa[8][4];
    #pragma unroll
    for (int kk = 0; kk < 8; kk++) {
        const float* q0p = &Qs[(w * 16 + grp    ) * APAD + kk * 8];
        const float* q1p = &Qs[(w * 16 + grp + 8) * APAD + kk * 8];
        qa[kk][0] = __float_as_uint(q0p[tig]);
        qa[kk][1] = __float_as_uint(q1p[tig]);
        qa[kk][2] = __float_as_uint(q0p[tig + 4]);
        qa[kk][3] = __float_as_uint(q1p[tig + 4]);
    }

    // per-thread K/V load slots (4 chunks each of K and V)
    uint32_t kdst[4], vdst[4];
    const float* ksrc[4];
    const float* vsrc[4];
    #pragma unroll
    for (int t = 0; t < 4; t++) {
        int idx = tid + t * 256;
        int r = idx >> 4, c4 = idx & 15;
        kdst[t] = smem_u32(&Ks[r * APAD + c4 * 4]);
        vdst[t] = smem_u32(&Vs[r * VPAD + c4 * 4]);
        ksrc[t] = &qkv[(rowbase + r) * LDQKV + colk + c4 * 4];
        vsrc[t] = &qkv[(rowbase + r) * LDQKV + colv + c4 * 4];
    }

    float o[8][4];
    #pragma unroll
    for (int ni = 0; ni < 8; ni++)
        #pragma unroll
        for (int c = 0; c < 4; c++) o[ni][c] = 0.f;
    float m0 = -1e30f, m1 = -1e30f, l0 = 0.f, l1 = 0.f;

    const int r0g = q0 + w * 16 + grp;
    const int r1g = r0g + 8;

    const int nkt = 2 * qt + 2;
    for (int kt = 0; kt < nkt; kt++) {
        const int k0 = kt * 64;
        __syncthreads();   // prior iter's P/V consumers done
        #pragma unroll
        for (int t = 0; t < 4; t++) {
            cp16(kdst[t], ksrc[t] + (size_t)k0 * LDQKV);
            cp16(vdst[t], vsrc[t] + (size_t)k0 * LDQKV);
        }
        cp_commit();
        cp_wait0();
        __syncthreads();

        // S = Q K^T
        float s[8][4];
        #pragma unroll
        for (int ni = 0; ni < 8; ni++)
            #pragma unroll
            for (int c = 0; c < 4; c++) s[ni][c] = 0.f;
        #pragma unroll
        for (int kk = 0; kk < 8; kk++) {
            #pragma unroll
            for (int ni = 0; ni < 8; ni++) {
                const float* kp = &Ks[(ni * 8 + grp) * APAD + kk * 8];
                uint32_t bfr[2];
                bfr[0] = __float_as_uint(kp[tig]);
                bfr[1] = __float_as_uint(kp[tig + 4]);
                mma_tf32(s[ni], qa[kk], bfr);
            }
        }
        #pragma unroll
        for (int ni = 0; ni < 8; ni++)
            #pragma unroll
            for (int c = 0; c < 4; c++) s[ni][c] *= 0.125f;

        if (k0 + 63 > r0g) {
            #pragma unroll
            for (int ni = 0; ni < 8; ni++) {
                int c0 = k0 + ni * 8 + 2 * tig;
                if (c0     > r0g) s[ni][0] = -1e30f;
                if (c0 + 1 > r0g) s[ni][1] = -1e30f;
                if (c0     > r1g) s[ni][2] = -1e30f;
                if (c0 + 1 > r1g) s[ni][3] = -1e30f;
            }
        }

        float pm0 = -1e30f, pm1 = -1e30f;
        #pragma unroll
        for (int ni = 0; ni < 8; ni++) {
            pm0 = fmaxf(pm0, fmaxf(s[ni][0], s[ni][1]));
            pm1 = fmaxf(pm1, fmaxf(s[ni][2], s[ni][3]));
        }
        pm0 = fmaxf(pm0, __shfl_xor_sync(0xffffffffu, pm0, 1));
        pm0 = fmaxf(pm0, __shfl_xor_sync(0xffffffffu, pm0, 2));
        pm1 = fmaxf(pm1, __shfl_xor_sync(0xffffffffu, pm1, 1));
        pm1 = fmaxf(pm1, __shfl_xor_sync(0xffffffffu, pm1, 2));
        float mn0 = fmaxf(m0, pm0), mn1 = fmaxf(m1, pm1);
        float a0 = __expf(m0 - mn0), a1 = __expf(m1 - mn1);
        m0 = mn0; m1 = mn1;

        float rs0 = 0.f, rs1 = 0.f;
        float* p0p = &Ps[(w * 16 + grp    ) * APAD + 2 * tig];
        float* p1p = &Ps[(w * 16 + grp + 8) * APAD + 2 * tig];
        #pragma unroll
        for (int ni = 0; ni < 8; ni++) {
            float e0 = __expf(s[ni][0] - mn0);
            float e1 = __expf(s[ni][1] - mn0);
            float e2 = __expf(s[ni][2] - mn1);
            float e3 = __expf(s[ni][3] - mn1);
            rs0 += e0 + e1; rs1 += e2 + e3;
            float2 w0 = { roundtf(e0), roundtf(e1) };
            float2 w1 = { roundtf(e2), roundtf(e3) };
            *(float2*)&p0p[ni * 8] = w0;
            *(float2*)&p1p[ni * 8] = w1;
        }
        rs0 += __shfl_xor_sync(0xffffffffu, rs0, 1);
        rs0 += __shfl_xor_sync(0xffffffffu, rs0, 2);
        rs1 += __shfl_xor_sync(0xffffffffu, rs1, 1);
        rs1 += __shfl_xor_sync(0xffffffffu, rs1, 2);
        l0 = l0 * a0 + rs0;
        l1 = l1 * a1 + rs1;

        #pragma unroll
        for (int ni = 0; ni < 8; ni++) {
            o[ni][0] *= a0; o[ni][1] *= a0;
            o[ni][2] *= a1; o[ni][3] *= a1;
        }
        __syncwarp();

        #pragma unroll
        for (int kk = 0; kk < 8; kk++) {
            const float* pa0 = &Ps[(w * 16 + grp    ) * APAD + kk * 8];
            const float* pa1 = &Ps[(w * 16 + grp + 8) * APAD + kk * 8];
            uint32_t pa[4];
            pa[0] = __float_as_uint(pa0[tig]);
            pa[1] = __float_as_uint(pa1[tig]);
            pa[2] = __float_as_uint(pa0[tig + 4]);
            pa[3] = __float_as_uint(pa1[tig + 4]);
            #pragma unroll
            for (int ni = 0; ni < 8; ni++) {
                uint32_t bfr[2];
                bfr[0] = __float_as_uint(Vs[(kk * 8 + tig    ) * VPAD + ni * 8 + grp]);
                bfr[1] = __float_as_uint(Vs[(kk * 8 + tig + 4) * VPAD + ni * 8 + grp]);
                mma_tf32(o[ni], pa, bfr);
            }
        }
    }

    float inv0 = 1.f / l0, inv1 = 1.f / l1;
    #pragma unroll
    for (int ni = 0; ni < 8; ni++) {
        int col = h * HD + ni * 8 + 2 * tig;
        float2 v0 = { roundtf(o[ni][0] * inv0), roundtf(o[ni][1] * inv0) };
        float2 v1 = { roundtf(o[ni][2] * inv1), roundtf(o[ni][3] * inv1) };
        *(float2*)&att[(rowbase + r0g) * EMB + col] = v0;
        *(float2*)&att[(rowbase + r1g) * EMB + col] = v1;
    }
}

// ---------------------------------------------------------------------------
extern "C" void kernel_launch(void* const* d_in, const int* in_sizes, int n_in,
                              void* d_out, int out_size)
{
    const float* x      = (const float*)d_in[0];
    const float* w_attn = (const float*)d_in[1];
    const float* b_attn = (const float*)d_in[2];
    const float* w_proj = (const float*)d_in[3];
    const float* b_proj = (const float*)d_in[4];
    float* out = (float*)d_out;

    float *qkv, *att, *xt, *wat, *wpt;
    cudaGetSymbolAddress((void**)&qkv, g_qkv);
    cudaGetSymbolAddress((void**)&att, g_att);
    cudaGetSymbolAddress((void**)&xt,  g_xt);
    cudaGetSymbolAddress((void**)&wat, g_wat);
    cudaGetSymbolAddress((void**)&wpt, g_wpt);

    cudaFuncSetAttribute(gemm_tf32, cudaFuncAttributeMaxDynamicSharedMemorySize, GEMM_SMEM_BYTES);
    cudaFuncSetAttribute(attn_mma,  cudaFuncAttributeMaxDynamicSharedMemorySize, ATTN_SMEM_BYTES);

    // 0) tf32 rounding prepass
    round_tf32_kernel<<<(MROWS * EMB / 4 + 255) / 256, 256>>>(x, xt, MROWS * EMB / 4);
    round_tf32_kernel<<<(EMB * LDQKV / 4 + 255) / 256, 256>>>(w_attn, wat, EMB * LDQKV / 4);
    round_tf32_kernel<<<(EMB * EMB / 4 + 255) / 256, 256>>>(w_proj, wpt, EMB * EMB / 4);

    // 1) qkv = x @ w_attn + b_attn
    {
        dim3 grid(LDQKV / BN, MROWS / BM);
        gemm_tf32<<<grid, GT, GEMM_SMEM_BYTES>>>(xt, wat, b_attn, qkv, LDQKV, EMB, 1);
    }
    // 2) tensor-core flash attention
    {
        dim3 grid(SEQ / 128, NH, BATCH);
        attn_mma<<<grid, 256, ATTN_SMEM_BYTES>>>(qkv, att);
    }
    // 3) out = att @ w_proj + b_proj
    {
        dim3 grid(EMB / BN, MROWS / BM);
        gemm_tf32<<<grid, GT, GEMM_SMEM_BYTES>>>(att, wpt, b_proj, out, EMB, EMB, 0);
    }
}